// round 1
// baseline (speedup 1.0000x reference)
#include <cuda_runtime.h>
#include <cuda_bf16.h>
#include <cstdint>

// Problem constants
#define BATCH 2
#define SEQ   2048
#define HDIM  768
#define IDIM  256
#define MTOK  (BATCH * SEQ)   // 4096 tokens

// ---------------------------------------------------------------------------
// Scratch (device globals; no allocation allowed)
// ---------------------------------------------------------------------------
__device__ float g_Q[MTOK * HDIM];
__device__ float g_K[MTOK * HDIM];
__device__ float g_V[MTOK * HDIM];
__device__ float g_attn[MTOK * HDIM];
__device__ float g_h0[MTOK * IDIM];
__device__ float g_qkvs[MTOK * 3 * IDIM];
__device__ float g_sattn[MTOK * IDIM];
__device__ float g_h1[MTOK * IDIM];
__device__ float g_biasS[MTOK];
__device__ float g_biasM[MTOK];

// ---------------------------------------------------------------------------
// mask -> additive bias for scorer attention
// ---------------------------------------------------------------------------
__global__ void mask_bias_kernel(const int* __restrict__ mask, float* __restrict__ biasS, int n) {
    int i = blockIdx.x * 256 + threadIdx.x;
    if (i < n) biasS[i] = (mask[i] > 0) ? 0.f : -1e9f;
}

// ---------------------------------------------------------------------------
// C[M,N] = A[M,K] @ W[N,K]^T + bias[N]   (torch nn.Linear)
// 64x64 tile, BK=16, 256 threads, 4x4 microtile. M%64==0, N%64==0, K%16==0.
// ---------------------------------------------------------------------------
__global__ __launch_bounds__(256) void gemm_bias_kernel(
    const float* __restrict__ A, const float* __restrict__ W,
    const float* __restrict__ bias, float* __restrict__ C,
    int M, int N, int K)
{
    const int BK = 16;
    __shared__ float As[BK][64];
    __shared__ float Ws[BK][64];

    int bm = blockIdx.y * 64;
    int bn = blockIdx.x * 64;
    int tid = threadIdx.x;
    int tx = tid & 15;       // 0..15 -> N microtile
    int ty = tid >> 4;       // 0..15 -> M microtile

    int lr = tid >> 2;        // 0..63 (row within tile for loads)
    int lc = (tid & 3) * 4;   // 0,4,8,12 (k offset)

    float acc[4][4];
    #pragma unroll
    for (int i = 0; i < 4; i++)
        #pragma unroll
        for (int j = 0; j < 4; j++) acc[i][j] = 0.f;

    const float* Arow = A + (size_t)(bm + lr) * K;
    const float* Wrow = W + (size_t)(bn + lr) * K;

    for (int k0 = 0; k0 < K; k0 += BK) {
        float4 av = *reinterpret_cast<const float4*>(Arow + k0 + lc);
        As[lc + 0][lr] = av.x; As[lc + 1][lr] = av.y;
        As[lc + 2][lr] = av.z; As[lc + 3][lr] = av.w;
        float4 wv = *reinterpret_cast<const float4*>(Wrow + k0 + lc);
        Ws[lc + 0][lr] = wv.x; Ws[lc + 1][lr] = wv.y;
        Ws[lc + 2][lr] = wv.z; Ws[lc + 3][lr] = wv.w;
        __syncthreads();

        #pragma unroll
        for (int k = 0; k < BK; k++) {
            float4 a4 = *reinterpret_cast<const float4*>(&As[k][ty * 4]);
            float4 b4 = *reinterpret_cast<const float4*>(&Ws[k][tx * 4]);
            float a[4] = {a4.x, a4.y, a4.z, a4.w};
            float b[4] = {b4.x, b4.y, b4.z, b4.w};
            #pragma unroll
            for (int i = 0; i < 4; i++)
                #pragma unroll
                for (int j = 0; j < 4; j++) acc[i][j] += a[i] * b[j];
        }
        __syncthreads();
    }

    #pragma unroll
    for (int i = 0; i < 4; i++) {
        float* crow = C + (size_t)(bm + ty * 4 + i) * N + bn + tx * 4;
        #pragma unroll
        for (int j = 0; j < 4; j++)
            crow[j] = acc[i][j] + bias[bn + tx * 4 + j];
    }
}

// ---------------------------------------------------------------------------
// Flash attention, head_dim = 64. One thread per query (128 q / block),
// 64-key tiles in smem, online softmax. Additive per-key bias (already
// includes mask and survival terms).
// Layouts: Q/K/V rows have leading dim `ld`; head h occupies columns
// [x_off + h*64, x_off + h*64 + 64). Output similarly with o_ld/o_off.
// ---------------------------------------------------------------------------
__global__ __launch_bounds__(128) void attn_kernel(
    const float* __restrict__ Qp, const float* __restrict__ Kp,
    const float* __restrict__ Vp, const float* __restrict__ bias,
    float* __restrict__ Op,
    int S, int ld, int q_off, int k_off, int v_off,
    int o_ld, int o_off, float scale)
{
    __shared__ float Ks[64][64];
    __shared__ float Vs[64][64];
    __shared__ float bs[64];

    int b = blockIdx.z;
    int h = blockIdx.y;
    int tid = threadIdx.x;
    int qi = blockIdx.x * 128 + tid;

    const float* qrow = Qp + (size_t)(b * S + qi) * ld + q_off + h * 64;
    float q[64];
    #pragma unroll
    for (int d = 0; d < 64; d += 4) {
        float4 t = *reinterpret_cast<const float4*>(qrow + d);
        q[d] = t.x; q[d + 1] = t.y; q[d + 2] = t.z; q[d + 3] = t.w;
    }

    float o[64];
    #pragma unroll
    for (int d = 0; d < 64; d++) o[d] = 0.f;
    float m = -1e30f, l = 0.f;

    int lrow = tid >> 1;         // 0..63
    int lcol = (tid & 1) * 32;   // 0 or 32

    for (int kt = 0; kt < S; kt += 64) {
        const float* kbase = Kp + (size_t)(b * S + kt + lrow) * ld + k_off + h * 64 + lcol;
        const float* vbase = Vp + (size_t)(b * S + kt + lrow) * ld + v_off + h * 64 + lcol;
        #pragma unroll
        for (int j = 0; j < 32; j += 4) {
            *reinterpret_cast<float4*>(&Ks[lrow][lcol + j]) =
                *reinterpret_cast<const float4*>(kbase + j);
            *reinterpret_cast<float4*>(&Vs[lrow][lcol + j]) =
                *reinterpret_cast<const float4*>(vbase + j);
        }
        if (tid < 64) bs[tid] = bias[(size_t)b * S + kt + tid];
        __syncthreads();

        #pragma unroll 2
        for (int j = 0; j < 64; j++) {
            float s = 0.f;
            #pragma unroll
            for (int d = 0; d < 64; d += 4) {
                float4 kk = *reinterpret_cast<const float4*>(&Ks[j][d]);
                s += q[d] * kk.x + q[d + 1] * kk.y + q[d + 2] * kk.z + q[d + 3] * kk.w;
            }
            s = s * scale + bs[j];
            if (s > m) {                       // rare after warm-up
                float corr = __expf(m - s);
                m = s;
                l *= corr;
                #pragma unroll
                for (int d = 0; d < 64; d++) o[d] *= corr;
            }
            float p = __expf(s - m);
            l += p;
            #pragma unroll
            for (int d = 0; d < 64; d += 4) {
                float4 vv = *reinterpret_cast<const float4*>(&Vs[j][d]);
                o[d]     += p * vv.x; o[d + 1] += p * vv.y;
                o[d + 2] += p * vv.z; o[d + 3] += p * vv.w;
            }
        }
        __syncthreads();
    }

    float inv = 1.f / l;
    float* orow = Op + (size_t)(b * S + qi) * o_ld + o_off + h * 64;
    #pragma unroll
    for (int d = 0; d < 64; d += 4) {
        float4 t;
        t.x = o[d] * inv; t.y = o[d + 1] * inv;
        t.z = o[d + 2] * inv; t.w = o[d + 3] * inv;
        *reinterpret_cast<float4*>(orow + d) = t;
    }
}

// ---------------------------------------------------------------------------
// Fused survival MLPs: H[tok, 256] -> n/mu/delta heads -> surv -> main bias.
// One block (128 threads) per token; thread t owns hidden unit t of each head.
// ---------------------------------------------------------------------------
__global__ __launch_bounds__(128) void mlp_surv_kernel(
    const float* __restrict__ H, const int* __restrict__ mask,
    const float* __restrict__ nw1, const float* __restrict__ nb1,
    const float* __restrict__ nw2, const float* __restrict__ nb2,
    const float* __restrict__ mw1, const float* __restrict__ mb1,
    const float* __restrict__ mw2, const float* __restrict__ mb2,
    const float* __restrict__ dw1, const float* __restrict__ db1,
    const float* __restrict__ dw2, const float* __restrict__ db2,
    float* __restrict__ biasM)
{
    __shared__ float hs[256];
    __shared__ float red[3][128];

    int tok = blockIdx.x;
    int t = threadIdx.x;

    hs[t]       = H[(size_t)tok * 256 + t];
    hs[t + 128] = H[(size_t)tok * 256 + 128 + t];
    __syncthreads();

    const float* wn = nw1 + (size_t)t * 256;
    const float* wm = mw1 + (size_t)t * 256;
    const float* wd = dw1 + (size_t)t * 256;
    float sn = 0.f, sm = 0.f, sd = 0.f;
    #pragma unroll 4
    for (int i = 0; i < 256; i++) {
        float hv = hs[i];
        sn += wn[i] * hv;
        sm += wm[i] * hv;
        sd += wd[i] * hv;
    }
    sn = fmaxf(sn + nb1[t], 0.f) * nw2[t];
    sm = fmaxf(sm + mb1[t], 0.f) * mw2[t];
    sd = fmaxf(sd + db1[t], 0.f) * dw2[t];
    red[0][t] = sn; red[1][t] = sm; red[2][t] = sd;
    __syncthreads();

    for (int s = 64; s > 0; s >>= 1) {
        if (t < s) {
            red[0][t] += red[0][t + s];
            red[1][t] += red[1][t + s];
            red[2][t] += red[2][t + s];
        }
        __syncthreads();
    }

    if (t == 0) {
        float zn = red[0][0] + nb2[0];
        float zm = red[1][0] + mb2[0];
        float zd = red[2][0] + db2[0];
        float n     = (zn > 20.f) ? zn : log1pf(__expf(zn));   // softplus
        float mu    = 1.f / (1.f + __expf(-zm));               // sigmoid
        float delta = fmaxf(zd, 0.f);                          // relu
        float surv  = logf(n + 1e-8f) + logf(mu + 1e-8f) - delta;
        biasM[tok] = 0.1f * surv + ((mask[tok] > 0) ? 0.f : -1e9f);
    }
}

// ---------------------------------------------------------------------------
// Launch
// ---------------------------------------------------------------------------
extern "C" void kernel_launch(void* const* d_in, const int* in_sizes, int n_in,
                              void* d_out, int out_size)
{
    const float* x        = (const float*)d_in[0];
    const int*   mask     = (const int*)  d_in[1];
    const float* qw = (const float*)d_in[2],  *qb = (const float*)d_in[3];
    const float* kw = (const float*)d_in[4],  *kb = (const float*)d_in[5];
    const float* vw = (const float*)d_in[6],  *vb = (const float*)d_in[7];
    const float* ow = (const float*)d_in[8],  *ob = (const float*)d_in[9];
    const float* sp_w = (const float*)d_in[10], *sp_b = (const float*)d_in[11];
    const float* sa_in_w  = (const float*)d_in[12], *sa_in_b  = (const float*)d_in[13];
    const float* sa_out_w = (const float*)d_in[14], *sa_out_b = (const float*)d_in[15];
    const float* nw1 = (const float*)d_in[16], *nb1 = (const float*)d_in[17];
    const float* nw2 = (const float*)d_in[18], *nb2 = (const float*)d_in[19];
    const float* mw1 = (const float*)d_in[20], *mb1 = (const float*)d_in[21];
    const float* mw2 = (const float*)d_in[22], *mb2 = (const float*)d_in[23];
    const float* dw1 = (const float*)d_in[24], *db1 = (const float*)d_in[25];
    const float* dw2 = (const float*)d_in[26], *db2 = (const float*)d_in[27];
    float* out = (float*)d_out;

    float *Q, *K, *V, *attn, *h0, *qkvs, *sattn, *h1, *biasS, *biasM;
    cudaGetSymbolAddress((void**)&Q,     g_Q);
    cudaGetSymbolAddress((void**)&K,     g_K);
    cudaGetSymbolAddress((void**)&V,     g_V);
    cudaGetSymbolAddress((void**)&attn,  g_attn);
    cudaGetSymbolAddress((void**)&h0,    g_h0);
    cudaGetSymbolAddress((void**)&qkvs,  g_qkvs);
    cudaGetSymbolAddress((void**)&sattn, g_sattn);
    cudaGetSymbolAddress((void**)&h1,    g_h1);
    cudaGetSymbolAddress((void**)&biasS, g_biasS);
    cudaGetSymbolAddress((void**)&biasM, g_biasM);

    const int M = MTOK, S = SEQ, B = BATCH, H = HDIM, I = IDIM;
    const float scale = 0.125f;   // 1/sqrt(64)

    // scorer path
    mask_bias_kernel<<<(M + 255) / 256, 256>>>(mask, biasS, M);
    gemm_bias_kernel<<<dim3(I / 64, M / 64), 256>>>(x, sp_w, sp_b, h0, M, I, H);
    gemm_bias_kernel<<<dim3(3 * I / 64, M / 64), 256>>>(h0, sa_in_w, sa_in_b, qkvs, M, 3 * I, I);
    attn_kernel<<<dim3(S / 128, 4, B), 128>>>(qkvs, qkvs, qkvs, biasS, sattn,
                                              S, 3 * I, 0, I, 2 * I, I, 0, scale);
    gemm_bias_kernel<<<dim3(I / 64, M / 64), 256>>>(sattn, sa_out_w, sa_out_b, h1, M, I, I);
    mlp_surv_kernel<<<M, 128>>>(h1, mask, nw1, nb1, nw2, nb2,
                                mw1, mb1, mw2, mb2, dw1, db1, dw2, db2, biasM);

    // main path
    gemm_bias_kernel<<<dim3(H / 64, M / 64), 256>>>(x, qw, qb, Q, M, H, H);
    gemm_bias_kernel<<<dim3(H / 64, M / 64), 256>>>(x, kw, kb, K, M, H, H);
    gemm_bias_kernel<<<dim3(H / 64, M / 64), 256>>>(x, vw, vb, V, M, H, H);
    attn_kernel<<<dim3(S / 128, 12, B), 128>>>(Q, K, V, biasM, attn,
                                               S, H, 0, 0, 0, H, 0, scale);
    gemm_bias_kernel<<<dim3(H / 64, M / 64), 256>>>(attn, ow, ob, out, M, H, H);
}

// round 3
// speedup vs baseline: 2.0915x; 2.0915x over previous
#include <cuda_runtime.h>
#include <cuda_bf16.h>
#include <cstdint>

#define BATCH 2
#define SEQ   2048
#define HDIM  768
#define IDIM  256
#define MTOK  (BATCH * SEQ)   // 4096 tokens

// ---------------------------------------------------------------------------
// Scratch (device globals; no allocation allowed)
// ---------------------------------------------------------------------------
__device__ float g_Q[MTOK * HDIM];
__device__ float g_K[MTOK * HDIM];
__device__ float g_V[MTOK * HDIM];
__device__ float g_attn[MTOK * HDIM];
__device__ float g_h0[MTOK * IDIM];
__device__ float g_qkvs[MTOK * 3 * IDIM];
__device__ float g_sattn[MTOK * IDIM];
__device__ float g_h1[MTOK * IDIM];
__device__ float g_biasS[MTOK];
__device__ float g_biasM[MTOK];

// ---------------------------------------------------------------------------
// Helpers: tf32 convert, exp2, m16n8k8 tf32 mma
// ---------------------------------------------------------------------------
__device__ __forceinline__ unsigned f2tf(float f) {
    unsigned r; asm("cvt.rna.tf32.f32 %0, %1;" : "=r"(r) : "f"(f)); return r;
}
__device__ __forceinline__ float ex2(float x) {
    float r; asm("ex2.approx.f32 %0, %1;" : "=f"(r) : "f"(x)); return r;
}
__device__ __forceinline__ void mma8(float c[4], const unsigned a[4], const unsigned b[2]) {
    asm volatile(
        "mma.sync.aligned.m16n8k8.row.col.f32.tf32.tf32.f32 "
        "{%0,%1,%2,%3},{%4,%5,%6,%7},{%8,%9},{%0,%1,%2,%3};"
        : "+f"(c[0]), "+f"(c[1]), "+f"(c[2]), "+f"(c[3])
        : "r"(a[0]), "r"(a[1]), "r"(a[2]), "r"(a[3]), "r"(b[0]), "r"(b[1]));
}

// ---------------------------------------------------------------------------
// mask -> additive bias (scorer attention)
// ---------------------------------------------------------------------------
__global__ void mask_bias_kernel(const int* __restrict__ mask, float* __restrict__ biasS, int n) {
    int i = blockIdx.x * 256 + threadIdx.x;
    if (i < n) biasS[i] = (mask[i] > 0) ? 0.f : -1e9f;
}

// ---------------------------------------------------------------------------
// tf32 tensor-core GEMM: C[M,N] = A[M,K] @ W[N,K]^T + bias[N]
// CTA tile 128x64, BK=32, 256 threads (8 warps as 4m x 2n, warp tile 32x32).
// Requires M%128==0, N%64==0, K%32==0.
// ---------------------------------------------------------------------------
#define GP 36   // smem row stride (pad): bank = (4g+tig)%32 -> conflict-free frags
__global__ __launch_bounds__(256) void gemm_tf32(
    const float* __restrict__ A, const float* __restrict__ W,
    const float* __restrict__ bias, float* __restrict__ C,
    int M, int N, int K)
{
    __shared__ unsigned As[128 * GP];
    __shared__ unsigned Bs[64 * GP];

    int tid = threadIdx.x;
    int warp = tid >> 5, lane = tid & 31, g = lane >> 2, tig = lane & 3;
    int wm = (warp & 3) * 32, wn = (warp >> 2) * 32;
    int bm = blockIdx.y * 128, bn = blockIdx.x * 64;

    float acc[2][4][4];
    #pragma unroll
    for (int mt = 0; mt < 2; mt++)
        #pragma unroll
        for (int nt = 0; nt < 4; nt++)
            #pragma unroll
            for (int i = 0; i < 4; i++) acc[mt][nt][i] = 0.f;

    for (int k0 = 0; k0 < K; k0 += 32) {
        #pragma unroll
        for (int i = 0; i < 4; i++) {               // A: 128x32 = 1024 float4
            int idx = tid + i * 256;
            int r = idx >> 3, s = (idx & 7) * 4;
            float4 v = *(const float4*)(A + (size_t)(bm + r) * K + k0 + s);
            unsigned* dst = &As[r * GP + s];
            dst[0] = f2tf(v.x); dst[1] = f2tf(v.y); dst[2] = f2tf(v.z); dst[3] = f2tf(v.w);
        }
        #pragma unroll
        for (int i = 0; i < 2; i++) {               // W: 64x32 = 512 float4
            int idx = tid + i * 256;
            int r = idx >> 3, s = (idx & 7) * 4;
            float4 v = *(const float4*)(W + (size_t)(bn + r) * K + k0 + s);
            unsigned* dst = &Bs[r * GP + s];
            dst[0] = f2tf(v.x); dst[1] = f2tf(v.y); dst[2] = f2tf(v.z); dst[3] = f2tf(v.w);
        }
        __syncthreads();

        #pragma unroll
        for (int ks = 0; ks < 4; ks++) {
            unsigned af[2][4], bf[4][2];
            #pragma unroll
            for (int mt = 0; mt < 2; mt++) {
                int r0 = wm + mt * 16 + g;
                af[mt][0] = As[r0 * GP + ks * 8 + tig];
                af[mt][1] = As[(r0 + 8) * GP + ks * 8 + tig];
                af[mt][2] = As[r0 * GP + ks * 8 + tig + 4];
                af[mt][3] = As[(r0 + 8) * GP + ks * 8 + tig + 4];
            }
            #pragma unroll
            for (int nt = 0; nt < 4; nt++) {
                int r0 = wn + nt * 8 + g;
                bf[nt][0] = Bs[r0 * GP + ks * 8 + tig];
                bf[nt][1] = Bs[r0 * GP + ks * 8 + tig + 4];
            }
            #pragma unroll
            for (int mt = 0; mt < 2; mt++)
                #pragma unroll
                for (int nt = 0; nt < 4; nt++)
                    mma8(acc[mt][nt], af[mt], bf[nt]);
        }
        __syncthreads();
    }

    #pragma unroll
    for (int mt = 0; mt < 2; mt++) {
        int row0 = bm + wm + mt * 16 + g;
        #pragma unroll
        for (int nt = 0; nt < 4; nt++) {
            int col = bn + wn + nt * 8 + 2 * tig;
            float b0 = __ldg(bias + col), b1 = __ldg(bias + col + 1);
            float2 v0 = make_float2(acc[mt][nt][0] + b0, acc[mt][nt][1] + b1);
            float2 v1 = make_float2(acc[mt][nt][2] + b0, acc[mt][nt][3] + b1);
            *(float2*)(C + (size_t)row0 * N + col) = v0;
            *(float2*)(C + (size_t)(row0 + 8) * N + col) = v1;
        }
    }
}

// ---------------------------------------------------------------------------
// Flash attention with tf32 mma, head_dim=64.
// Block: 128 threads (4 warps), 64 queries; key tile = 32; online softmax in
// exp2 domain. Per-key additive bias (mask/survival already folded in).
// Head h occupies cols [off + h*64, off + h*64 + 64) of rows with stride ld.
// ---------------------------------------------------------------------------
__global__ __launch_bounds__(128) void attn_tf32(
    const float* __restrict__ Qp, const float* __restrict__ Kp,
    const float* __restrict__ Vp, const float* __restrict__ bias,
    float* __restrict__ Op,
    int S, int ld, int q_off, int k_off, int v_off, int o_ld, int o_off)
{
    __shared__ unsigned KV[64 * 68];   // rows 0-31: K tile; rows 32-63: V tile (also Q staging)
    __shared__ unsigned Ps[64 * 36];   // per-warp P tiles (warp w: rows w*16..w*16+15)
    __shared__ float bsL[32];

    const float LOG2E = 1.4426950408889634f;
    int b = blockIdx.z, h = blockIdx.y;
    int q0 = blockIdx.x * 64;
    int tid = threadIdx.x, warp = tid >> 5, lane = tid & 31, g = lane >> 2, tig = lane & 3;

    // ---- stage Q tile (64x64) and load persistent A fragments ----
    const float* qbase = Qp + q_off + h * 64;
    #pragma unroll
    for (int i = 0; i < 8; i++) {
        int idx = tid + i * 128; int r = idx >> 4, s = (idx & 15) * 4;
        float4 v = *(const float4*)(qbase + (size_t)(b * S + q0 + r) * ld + s);
        unsigned* dst = &KV[r * 68 + s];
        dst[0] = f2tf(v.x); dst[1] = f2tf(v.y); dst[2] = f2tf(v.z); dst[3] = f2tf(v.w);
    }
    __syncthreads();
    unsigned qf[8][4];
    int qr = warp * 16;
    #pragma unroll
    for (int ks = 0; ks < 8; ks++) {
        qf[ks][0] = KV[(qr + g) * 68 + ks * 8 + tig];
        qf[ks][1] = KV[(qr + g + 8) * 68 + ks * 8 + tig];
        qf[ks][2] = KV[(qr + g) * 68 + ks * 8 + tig + 4];
        qf[ks][3] = KV[(qr + g + 8) * 68 + ks * 8 + tig + 4];
    }
    __syncthreads();

    float o[8][4];
    #pragma unroll
    for (int nt = 0; nt < 8; nt++)
        #pragma unroll
        for (int i = 0; i < 4; i++) o[nt][i] = 0.f;
    float m0 = -1e30f, m1 = -1e30f, l0 = 0.f, l1 = 0.f;
    const float sc = 0.125f * LOG2E;

    const float* kbase = Kp + k_off + h * 64;
    const float* vbase = Vp + v_off + h * 64;
    unsigned* pw = &Ps[warp * 16 * 36];

    for (int kt = 0; kt < S; kt += 32) {
        // ---- stage K/V tiles (32x64 each) + bias ----
        #pragma unroll
        for (int i = 0; i < 4; i++) {
            int idx = tid + i * 128; int r = idx >> 4, s = (idx & 15) * 4;
            size_t rowoff = (size_t)(b * S + kt + r) * ld + s;
            float4 kv4 = *(const float4*)(kbase + rowoff);
            unsigned* dk = &KV[r * 68 + s];
            dk[0] = f2tf(kv4.x); dk[1] = f2tf(kv4.y); dk[2] = f2tf(kv4.z); dk[3] = f2tf(kv4.w);
            float4 vv4 = *(const float4*)(vbase + rowoff);
            unsigned* dv = &KV[(32 + r) * 68 + s];
            dv[0] = f2tf(vv4.x); dv[1] = f2tf(vv4.y); dv[2] = f2tf(vv4.z); dv[3] = f2tf(vv4.w);
        }
        if (tid < 32) bsL[tid] = bias[(size_t)b * S + kt + tid] * LOG2E;
        __syncthreads();

        // ---- S = Q K^T (16 rows/warp x 32 keys) ----
        float sa[4][4];
        #pragma unroll
        for (int nt = 0; nt < 4; nt++)
            #pragma unroll
            for (int i = 0; i < 4; i++) sa[nt][i] = 0.f;
        #pragma unroll
        for (int ks = 0; ks < 8; ks++) {
            unsigned bf[4][2];
            #pragma unroll
            for (int nt = 0; nt < 4; nt++) {
                bf[nt][0] = KV[(nt * 8 + g) * 68 + ks * 8 + tig];
                bf[nt][1] = KV[(nt * 8 + g) * 68 + ks * 8 + tig + 4];
            }
            #pragma unroll
            for (int nt = 0; nt < 4; nt++) mma8(sa[nt], qf[ks], bf[nt]);
        }

        // ---- online softmax (exp2 domain), rows g (c0,c1) and g+8 (c2,c3) ----
        float rm0 = -1e30f, rm1 = -1e30f;
        #pragma unroll
        for (int nt = 0; nt < 4; nt++) {
            float bl0 = bsL[nt * 8 + 2 * tig], bl1 = bsL[nt * 8 + 2 * tig + 1];
            sa[nt][0] = sa[nt][0] * sc + bl0;
            sa[nt][1] = sa[nt][1] * sc + bl1;
            sa[nt][2] = sa[nt][2] * sc + bl0;
            sa[nt][3] = sa[nt][3] * sc + bl1;
            rm0 = fmaxf(rm0, fmaxf(sa[nt][0], sa[nt][1]));
            rm1 = fmaxf(rm1, fmaxf(sa[nt][2], sa[nt][3]));
        }
        rm0 = fmaxf(rm0, __shfl_xor_sync(0xffffffffu, rm0, 1));
        rm0 = fmaxf(rm0, __shfl_xor_sync(0xffffffffu, rm0, 2));
        rm1 = fmaxf(rm1, __shfl_xor_sync(0xffffffffu, rm1, 1));
        rm1 = fmaxf(rm1, __shfl_xor_sync(0xffffffffu, rm1, 2));
        float mn0 = fmaxf(m0, rm0), mn1 = fmaxf(m1, rm1);
        float c0 = ex2(m0 - mn0), c1 = ex2(m1 - mn1);
        float rs0 = 0.f, rs1 = 0.f;
        #pragma unroll
        for (int nt = 0; nt < 4; nt++) {
            sa[nt][0] = ex2(sa[nt][0] - mn0);
            sa[nt][1] = ex2(sa[nt][1] - mn0);
            sa[nt][2] = ex2(sa[nt][2] - mn1);
            sa[nt][3] = ex2(sa[nt][3] - mn1);
            rs0 += sa[nt][0] + sa[nt][1];
            rs1 += sa[nt][2] + sa[nt][3];
        }
        rs0 += __shfl_xor_sync(0xffffffffu, rs0, 1);
        rs0 += __shfl_xor_sync(0xffffffffu, rs0, 2);
        rs1 += __shfl_xor_sync(0xffffffffu, rs1, 1);
        rs1 += __shfl_xor_sync(0xffffffffu, rs1, 2);
        l0 = l0 * c0 + rs0; l1 = l1 * c1 + rs1;
        m0 = mn0; m1 = mn1;
        #pragma unroll
        for (int nt = 0; nt < 8; nt++) {
            o[nt][0] *= c0; o[nt][1] *= c0; o[nt][2] *= c1; o[nt][3] *= c1;
        }

        // ---- P -> per-warp smem (tf32), re-fragment for A ----
        #pragma unroll
        for (int nt = 0; nt < 4; nt++) {
            int cc = nt * 8 + 2 * tig;
            pw[g * 36 + cc]           = f2tf(sa[nt][0]);
            pw[g * 36 + cc + 1]       = f2tf(sa[nt][1]);
            pw[(g + 8) * 36 + cc]     = f2tf(sa[nt][2]);
            pw[(g + 8) * 36 + cc + 1] = f2tf(sa[nt][3]);
        }
        __syncwarp();

        // ---- O += P V (k over 32 keys, 64 d-cols) ----
        #pragma unroll
        for (int ks = 0; ks < 4; ks++) {
            unsigned af[4];
            af[0] = pw[g * 36 + ks * 8 + tig];
            af[1] = pw[(g + 8) * 36 + ks * 8 + tig];
            af[2] = pw[g * 36 + ks * 8 + tig + 4];
            af[3] = pw[(g + 8) * 36 + ks * 8 + tig + 4];
            #pragma unroll
            for (int nt = 0; nt < 8; nt++) {
                unsigned bf2[2];
                bf2[0] = KV[(32 + ks * 8 + tig) * 68 + nt * 8 + g];
                bf2[1] = KV[(32 + ks * 8 + tig + 4) * 68 + nt * 8 + g];
                mma8(o[nt], af, bf2);
            }
        }
        __syncthreads();
    }

    // ---- normalize + write ----
    float inv0 = 1.f / l0, inv1 = 1.f / l1;
    int row0 = b * S + q0 + warp * 16 + g;
    float* ob0 = Op + o_off + h * 64 + (size_t)row0 * o_ld;
    float* ob1 = Op + o_off + h * 64 + (size_t)(row0 + 8) * o_ld;
    #pragma unroll
    for (int nt = 0; nt < 8; nt++) {
        int col = nt * 8 + 2 * tig;
        *(float2*)(ob0 + col) = make_float2(o[nt][0] * inv0, o[nt][1] * inv0);
        *(float2*)(ob1 + col) = make_float2(o[nt][2] * inv1, o[nt][3] * inv1);
    }
}

// ---------------------------------------------------------------------------
// Fused survival MLPs -> main-attention bias (per token)
// ---------------------------------------------------------------------------
__global__ __launch_bounds__(128) void mlp_surv_kernel(
    const float* __restrict__ H, const int* __restrict__ mask,
    const float* __restrict__ nw1, const float* __restrict__ nb1,
    const float* __restrict__ nw2, const float* __restrict__ nb2,
    const float* __restrict__ mw1, const float* __restrict__ mb1,
    const float* __restrict__ mw2, const float* __restrict__ mb2,
    const float* __restrict__ dw1, const float* __restrict__ db1,
    const float* __restrict__ dw2, const float* __restrict__ db2,
    float* __restrict__ biasM)
{
    __shared__ float hs[256];
    __shared__ float red[3][128];

    int tok = blockIdx.x;
    int t = threadIdx.x;

    hs[t]       = H[(size_t)tok * 256 + t];
    hs[t + 128] = H[(size_t)tok * 256 + 128 + t];
    __syncthreads();

    const float* wn = nw1 + (size_t)t * 256;
    const float* wm = mw1 + (size_t)t * 256;
    const float* wd = dw1 + (size_t)t * 256;
    float sn = 0.f, sm = 0.f, sd = 0.f;
    #pragma unroll 4
    for (int i = 0; i < 256; i++) {
        float hv = hs[i];
        sn += wn[i] * hv;
        sm += wm[i] * hv;
        sd += wd[i] * hv;
    }
    sn = fmaxf(sn + nb1[t], 0.f) * nw2[t];
    sm = fmaxf(sm + mb1[t], 0.f) * mw2[t];
    sd = fmaxf(sd + db1[t], 0.f) * dw2[t];
    red[0][t] = sn; red[1][t] = sm; red[2][t] = sd;
    __syncthreads();

    for (int s = 64; s > 0; s >>= 1) {
        if (t < s) {
            red[0][t] += red[0][t + s];
            red[1][t] += red[1][t + s];
            red[2][t] += red[2][t + s];
        }
        __syncthreads();
    }

    if (t == 0) {
        float zn = red[0][0] + nb2[0];
        float zm = red[1][0] + mb2[0];
        float zd = red[2][0] + db2[0];
        float n     = (zn > 20.f) ? zn : log1pf(__expf(zn));
        float mu    = 1.f / (1.f + __expf(-zm));
        float delta = fmaxf(zd, 0.f);
        float surv  = logf(n + 1e-8f) + logf(mu + 1e-8f) - delta;
        biasM[tok] = 0.1f * surv + ((mask[tok] > 0) ? 0.f : -1e9f);
    }
}

// ---------------------------------------------------------------------------
// Launch
// ---------------------------------------------------------------------------
extern "C" void kernel_launch(void* const* d_in, const int* in_sizes, int n_in,
                              void* d_out, int out_size)
{
    const float* x        = (const float*)d_in[0];
    const int*   mask     = (const int*)  d_in[1];
    const float* qw = (const float*)d_in[2],  *qb = (const float*)d_in[3];
    const float* kw = (const float*)d_in[4],  *kb = (const float*)d_in[5];
    const float* vw = (const float*)d_in[6],  *vb = (const float*)d_in[7];
    const float* ow = (const float*)d_in[8],  *ob = (const float*)d_in[9];
    const float* sp_w = (const float*)d_in[10], *sp_b = (const float*)d_in[11];
    const float* sa_in_w  = (const float*)d_in[12], *sa_in_b  = (const float*)d_in[13];
    const float* sa_out_w = (const float*)d_in[14], *sa_out_b = (const float*)d_in[15];
    const float* nw1 = (const float*)d_in[16], *nb1 = (const float*)d_in[17];
    const float* nw2 = (const float*)d_in[18], *nb2 = (const float*)d_in[19];
    const float* mw1 = (const float*)d_in[20], *mb1 = (const float*)d_in[21];
    const float* mw2 = (const float*)d_in[22], *mb2 = (const float*)d_in[23];
    const float* dw1 = (const float*)d_in[24], *db1 = (const float*)d_in[25];
    const float* dw2 = (const float*)d_in[26], *db2 = (const float*)d_in[27];
    float* out = (float*)d_out;

    float *Q, *K, *V, *attn, *h0, *qkvs, *sattn, *h1, *biasS, *biasM;
    cudaGetSymbolAddress((void**)&Q,     g_Q);
    cudaGetSymbolAddress((void**)&K,     g_K);
    cudaGetSymbolAddress((void**)&V,     g_V);
    cudaGetSymbolAddress((void**)&attn,  g_attn);
    cudaGetSymbolAddress((void**)&h0,    g_h0);
    cudaGetSymbolAddress((void**)&qkvs,  g_qkvs);
    cudaGetSymbolAddress((void**)&sattn, g_sattn);
    cudaGetSymbolAddress((void**)&h1,    g_h1);
    cudaGetSymbolAddress((void**)&biasS, g_biasS);
    cudaGetSymbolAddress((void**)&biasM, g_biasM);

    const int M = MTOK, S = SEQ, B = BATCH, H = HDIM, I = IDIM;

    // scorer path
    mask_bias_kernel<<<(M + 255) / 256, 256>>>(mask, biasS, M);
    gemm_tf32<<<dim3(I / 64, M / 128), 256>>>(x, sp_w, sp_b, h0, M, I, H);
    gemm_tf32<<<dim3(3 * I / 64, M / 128), 256>>>(h0, sa_in_w, sa_in_b, qkvs, M, 3 * I, I);
    attn_tf32<<<dim3(S / 64, 4, B), 128>>>(qkvs, qkvs, qkvs, biasS, sattn,
                                           S, 3 * I, 0, I, 2 * I, I, 0);
    gemm_tf32<<<dim3(I / 64, M / 128), 256>>>(sattn, sa_out_w, sa_out_b, h1, M, I, I);
    mlp_surv_kernel<<<M, 128>>>(h1, mask, nw1, nb1, nw2, nb2,
                                mw1, mb1, mw2, mb2, dw1, db1, dw2, db2, biasM);

    // main path
    gemm_tf32<<<dim3(H / 64, M / 128), 256>>>(x, qw, qb, Q, M, H, H);
    gemm_tf32<<<dim3(H / 64, M / 128), 256>>>(x, kw, kb, K, M, H, H);
    gemm_tf32<<<dim3(H / 64, M / 128), 256>>>(x, vw, vb, V, M, H, H);
    attn_tf32<<<dim3(S / 64, 12, B), 128>>>(Q, K, V, biasM, attn,
                                            S, H, 0, 0, 0, H, 0);
    gemm_tf32<<<dim3(H / 64, M / 128), 256>>>(attn, ow, ob, out, M, H, H);
}

// round 4
// speedup vs baseline: 4.8682x; 2.3276x over previous
#include <cuda_runtime.h>
#include <cuda_bf16.h>
#include <cstdint>

#define BATCH 2
#define SEQ   2048
#define HDIM  768
#define IDIM  256
#define MTOK  (BATCH * SEQ)   // 4096 tokens

// ---------------------------------------------------------------------------
// Scratch (device globals; no allocation allowed)
// ---------------------------------------------------------------------------
__device__ float g_Q[MTOK * HDIM];
__device__ float g_K[MTOK * HDIM];
__device__ float g_V[MTOK * HDIM];
__device__ float g_attn[MTOK * HDIM];
__device__ float g_h0[MTOK * IDIM];
__device__ float g_qkvs[MTOK * 3 * IDIM];
__device__ float g_sattn[MTOK * IDIM];
__device__ float g_h1[MTOK * IDIM];
__device__ float g_biasS[MTOK];
__device__ float g_biasM[MTOK];

// ---------------------------------------------------------------------------
// Helpers
// ---------------------------------------------------------------------------
__device__ __forceinline__ unsigned f2tf(float f) {
    unsigned r; asm("cvt.rna.tf32.f32 %0, %1;" : "=r"(r) : "f"(f)); return r;
}
__device__ __forceinline__ float ex2(float x) {
    float r; asm("ex2.approx.f32 %0, %1;" : "=f"(r) : "f"(x)); return r;
}
__device__ __forceinline__ void mma8(float c[4], const unsigned a[4], const unsigned b[2]) {
    asm volatile(
        "mma.sync.aligned.m16n8k8.row.col.f32.tf32.tf32.f32 "
        "{%0,%1,%2,%3},{%4,%5,%6,%7},{%8,%9},{%0,%1,%2,%3};"
        : "+f"(c[0]), "+f"(c[1]), "+f"(c[2]), "+f"(c[3])
        : "r"(a[0]), "r"(a[1]), "r"(a[2]), "r"(a[3]), "r"(b[0]), "r"(b[1]));
}
__device__ __forceinline__ unsigned s2u(const void* p) {
    return (unsigned)__cvta_generic_to_shared(p);
}
__device__ __forceinline__ void cp16(unsigned dst, const void* src) {
    asm volatile("cp.async.ca.shared.global [%0], [%1], 16;" :: "r"(dst), "l"(src));
}
__device__ __forceinline__ void cp_commit() { asm volatile("cp.async.commit_group;"); }
__device__ __forceinline__ void cp_wait0() { asm volatile("cp.async.wait_group 0;"); }
__device__ __forceinline__ void cp_wait1() { asm volatile("cp.async.wait_group 1;"); }

// ---------------------------------------------------------------------------
// mask -> additive bias (scorer attention)
// ---------------------------------------------------------------------------
__global__ void mask_bias_kernel(const int* __restrict__ mask, float* __restrict__ biasS, int n) {
    int i = blockIdx.x * 256 + threadIdx.x;
    if (i < n) biasS[i] = (mask[i] > 0) ? 0.f : -1e9f;
}

// ---------------------------------------------------------------------------
// GEMM v2: C[M,N] = A[M,K] @ W[N,K]^T + bias[N]
// BM x 128 CTA tile (BM=128 or 64), BK=32, 256 threads, cp.async 2-stage.
// Warps: 2(m) x 4(n); warp tile (BM/2) x 32. tf32 cvt at fragment load.
// ---------------------------------------------------------------------------
template<int BM>
__global__ __launch_bounds__(256) void gemm2(
    const float* __restrict__ A, const float* __restrict__ W,
    const float* __restrict__ bias, float* __restrict__ C,
    int M, int N, int K)
{
    constexpr int MFRAG = BM / 32;          // m16 frags per warp (4 or 2)
    extern __shared__ float smemf[];
    float* As = smemf;                       // [2][BM*36]
    float* Bs = smemf + 2 * BM * 36;         // [2][128*36]

    int tid = threadIdx.x, warp = tid >> 5, lane = tid & 31, g = lane >> 2, tig = lane & 3;
    int wm = (warp & 1) * (BM / 2), wn = (warp >> 1) * 32;
    int bm = blockIdx.y * BM, bn = blockIdx.x * 128;

    float acc[MFRAG][4][4];
    #pragma unroll
    for (int mt = 0; mt < MFRAG; mt++)
        #pragma unroll
        for (int nt = 0; nt < 4; nt++)
            #pragma unroll
            for (int i = 0; i < 4; i++) acc[mt][nt][i] = 0.f;

    auto issue = [&](int stage, int k0) {
        #pragma unroll
        for (int i = 0; i < BM / 32; i++) {          // A: BM*8 float4
            int idx = tid + i * 256;
            int r = idx >> 3, c4 = (idx & 7) * 4;
            cp16(s2u(&As[stage * BM * 36 + r * 36 + c4]),
                 A + (size_t)(bm + r) * K + k0 + c4);
        }
        #pragma unroll
        for (int i = 0; i < 4; i++) {                // B: 128*8 float4
            int idx = tid + i * 256;
            int r = idx >> 3, c4 = (idx & 7) * 4;
            cp16(s2u(&Bs[stage * 128 * 36 + r * 36 + c4]),
                 W + (size_t)(bn + r) * K + k0 + c4);
        }
        cp_commit();
    };

    int ntiles = K / 32;
    issue(0, 0);
    for (int t = 0; t < ntiles; t++) {
        if (t + 1 < ntiles) { issue((t + 1) & 1, (t + 1) * 32); cp_wait1(); }
        else                { cp_wait0(); }
        __syncthreads();

        const float* as = As + (t & 1) * BM * 36;
        const float* bs = Bs + (t & 1) * 128 * 36;
        #pragma unroll
        for (int ks = 0; ks < 4; ks++) {
            unsigned af[MFRAG][4], bf[4][2];
            #pragma unroll
            for (int mt = 0; mt < MFRAG; mt++) {
                int r0 = wm + mt * 16 + g;
                af[mt][0] = f2tf(as[r0 * 36 + ks * 8 + tig]);
                af[mt][1] = f2tf(as[(r0 + 8) * 36 + ks * 8 + tig]);
                af[mt][2] = f2tf(as[r0 * 36 + ks * 8 + tig + 4]);
                af[mt][3] = f2tf(as[(r0 + 8) * 36 + ks * 8 + tig + 4]);
            }
            #pragma unroll
            for (int nt = 0; nt < 4; nt++) {
                int r0 = wn + nt * 8 + g;
                bf[nt][0] = f2tf(bs[r0 * 36 + ks * 8 + tig]);
                bf[nt][1] = f2tf(bs[r0 * 36 + ks * 8 + tig + 4]);
            }
            #pragma unroll
            for (int mt = 0; mt < MFRAG; mt++)
                #pragma unroll
                for (int nt = 0; nt < 4; nt++)
                    mma8(acc[mt][nt], af[mt], bf[nt]);
        }
        __syncthreads();
    }

    #pragma unroll
    for (int mt = 0; mt < MFRAG; mt++) {
        int row0 = bm + wm + mt * 16 + g;
        #pragma unroll
        for (int nt = 0; nt < 4; nt++) {
            int col = bn + wn + nt * 8 + 2 * tig;
            float b0 = __ldg(bias + col), b1 = __ldg(bias + col + 1);
            *(float2*)(C + (size_t)row0 * N + col) =
                make_float2(acc[mt][nt][0] + b0, acc[mt][nt][1] + b1);
            *(float2*)(C + (size_t)(row0 + 8) * N + col) =
                make_float2(acc[mt][nt][2] + b0, acc[mt][nt][3] + b1);
        }
    }
}

// ---------------------------------------------------------------------------
// Flash attention v2 (tf32 mma, head_dim=64): 256 threads / 8 warps,
// 128 queries per block, 64-key tiles, register-prefetch pipeline.
// Dynamic smem: KV[128][68] (K rows 0-63, V rows 64-127), Ps[128][68]
// (Q staging, then per-warp P tiles), bsL[64].
// ---------------------------------------------------------------------------
__global__ __launch_bounds__(256) void attn2(
    const float* __restrict__ Qp, const float* __restrict__ Kp,
    const float* __restrict__ Vp, const float* __restrict__ bias,
    float* __restrict__ Op,
    int S, int ld, int q_off, int k_off, int v_off, int o_ld, int o_off)
{
    extern __shared__ unsigned sm[];
    unsigned* KV = sm;                   // [128][68]
    unsigned* Ps = sm + 128 * 68;        // [128][68]
    float* bsL = (float*)(sm + 2 * 128 * 68);

    const float LOG2E = 1.4426950408889634f;
    int b = blockIdx.z, h = blockIdx.y, q0 = blockIdx.x * 128;
    int tid = threadIdx.x, warp = tid >> 5, lane = tid & 31, g = lane >> 2, tig = lane & 3;

    // ---- stage Q (128x64) into Ps, load persistent fragments ----
    const float* qbase = Qp + q_off + h * 64;
    #pragma unroll
    for (int i = 0; i < 8; i++) {
        int idx = tid + i * 256; int r = idx >> 4, s = (idx & 15) * 4;
        float4 v = *(const float4*)(qbase + (size_t)(b * S + q0 + r) * ld + s);
        unsigned* d = &Ps[r * 68 + s];
        d[0] = f2tf(v.x); d[1] = f2tf(v.y); d[2] = f2tf(v.z); d[3] = f2tf(v.w);
    }
    __syncthreads();
    unsigned qf[8][4];
    int qr = warp * 16;
    #pragma unroll
    for (int ks = 0; ks < 8; ks++) {
        qf[ks][0] = Ps[(qr + g) * 68 + ks * 8 + tig];
        qf[ks][1] = Ps[(qr + g + 8) * 68 + ks * 8 + tig];
        qf[ks][2] = Ps[(qr + g) * 68 + ks * 8 + tig + 4];
        qf[ks][3] = Ps[(qr + g + 8) * 68 + ks * 8 + tig + 4];
    }

    float o[8][4];
    #pragma unroll
    for (int nt = 0; nt < 8; nt++)
        #pragma unroll
        for (int i = 0; i < 4; i++) o[nt][i] = 0.f;
    float m0 = -1e30f, m1 = -1e30f, l0 = 0.f, l1 = 0.f;
    const float sc = 0.125f * LOG2E;

    const float* kbase = Kp + k_off + h * 64;
    const float* vbase = Vp + v_off + h * 64;
    unsigned* pw = Ps + warp * 16 * 68;

    int lr = tid >> 4, lc = (tid & 15) * 4;   // staging map: 64 rows x 16 float4

    // ---- prologue: stage tile 0 ----
    #pragma unroll
    for (int i = 0; i < 4; i++) {
        int r = lr + i * 16;
        size_t off = (size_t)(b * S + r) * ld + lc;
        float4 k4 = *(const float4*)(kbase + off);
        unsigned* dk = &KV[r * 68 + lc];
        dk[0] = f2tf(k4.x); dk[1] = f2tf(k4.y); dk[2] = f2tf(k4.z); dk[3] = f2tf(k4.w);
        float4 v4 = *(const float4*)(vbase + off);
        unsigned* dv = &KV[(64 + r) * 68 + lc];
        dv[0] = f2tf(v4.x); dv[1] = f2tf(v4.y); dv[2] = f2tf(v4.z); dv[3] = f2tf(v4.w);
    }
    if (tid < 64) bsL[tid] = bias[(size_t)b * S + tid] * LOG2E;
    __syncthreads();

    for (int kt = 0; kt < S; kt += 64) {
        bool nx = (kt + 64) < S;
        float4 kpre[4], vpre[4]; float bpre = 0.f;
        if (nx) {
            #pragma unroll
            for (int i = 0; i < 4; i++) {
                int r = lr + i * 16;
                size_t off = (size_t)(b * S + kt + 64 + r) * ld + lc;
                kpre[i] = *(const float4*)(kbase + off);
                vpre[i] = *(const float4*)(vbase + off);
            }
            if (tid < 64) bpre = bias[(size_t)b * S + kt + 64 + tid];
        }

        // ---- S = Q K^T : 16 rows/warp x 64 keys ----
        float sa[8][4];
        #pragma unroll
        for (int nt = 0; nt < 8; nt++)
            #pragma unroll
            for (int i = 0; i < 4; i++) sa[nt][i] = 0.f;
        #pragma unroll
        for (int ks = 0; ks < 8; ks++) {
            unsigned bf[8][2];
            #pragma unroll
            for (int nt = 0; nt < 8; nt++) {
                bf[nt][0] = KV[(nt * 8 + g) * 68 + ks * 8 + tig];
                bf[nt][1] = KV[(nt * 8 + g) * 68 + ks * 8 + tig + 4];
            }
            #pragma unroll
            for (int nt = 0; nt < 8; nt++) mma8(sa[nt], qf[ks], bf[nt]);
        }

        // ---- online softmax (exp2 domain) ----
        float rm0 = -1e30f, rm1 = -1e30f;
        #pragma unroll
        for (int nt = 0; nt < 8; nt++) {
            float bl0 = bsL[nt * 8 + 2 * tig], bl1 = bsL[nt * 8 + 2 * tig + 1];
            sa[nt][0] = sa[nt][0] * sc + bl0;
            sa[nt][1] = sa[nt][1] * sc + bl1;
            sa[nt][2] = sa[nt][2] * sc + bl0;
            sa[nt][3] = sa[nt][3] * sc + bl1;
            rm0 = fmaxf(rm0, fmaxf(sa[nt][0], sa[nt][1]));
            rm1 = fmaxf(rm1, fmaxf(sa[nt][2], sa[nt][3]));
        }
        rm0 = fmaxf(rm0, __shfl_xor_sync(0xffffffffu, rm0, 1));
        rm0 = fmaxf(rm0, __shfl_xor_sync(0xffffffffu, rm0, 2));
        rm1 = fmaxf(rm1, __shfl_xor_sync(0xffffffffu, rm1, 1));
        rm1 = fmaxf(rm1, __shfl_xor_sync(0xffffffffu, rm1, 2));
        float mn0 = fmaxf(m0, rm0), mn1 = fmaxf(m1, rm1);
        float c0 = ex2(m0 - mn0), c1 = ex2(m1 - mn1);
        float rs0 = 0.f, rs1 = 0.f;
        #pragma unroll
        for (int nt = 0; nt < 8; nt++) {
            sa[nt][0] = ex2(sa[nt][0] - mn0);
            sa[nt][1] = ex2(sa[nt][1] - mn0);
            sa[nt][2] = ex2(sa[nt][2] - mn1);
            sa[nt][3] = ex2(sa[nt][3] - mn1);
            rs0 += sa[nt][0] + sa[nt][1];
            rs1 += sa[nt][2] + sa[nt][3];
        }
        rs0 += __shfl_xor_sync(0xffffffffu, rs0, 1);
        rs0 += __shfl_xor_sync(0xffffffffu, rs0, 2);
        rs1 += __shfl_xor_sync(0xffffffffu, rs1, 1);
        rs1 += __shfl_xor_sync(0xffffffffu, rs1, 2);
        l0 = l0 * c0 + rs0; l1 = l1 * c1 + rs1;
        m0 = mn0; m1 = mn1;
        #pragma unroll
        for (int nt = 0; nt < 8; nt++) {
            o[nt][0] *= c0; o[nt][1] *= c0; o[nt][2] *= c1; o[nt][3] *= c1;
        }

        // ---- P -> per-warp smem (tf32) ----
        #pragma unroll
        for (int nt = 0; nt < 8; nt++) {
            int cc = nt * 8 + 2 * tig;
            pw[g * 68 + cc]           = f2tf(sa[nt][0]);
            pw[g * 68 + cc + 1]       = f2tf(sa[nt][1]);
            pw[(g + 8) * 68 + cc]     = f2tf(sa[nt][2]);
            pw[(g + 8) * 68 + cc + 1] = f2tf(sa[nt][3]);
        }
        __syncwarp();

        // ---- O += P V ----
        #pragma unroll
        for (int ks = 0; ks < 8; ks++) {
            unsigned af[4];
            af[0] = pw[g * 68 + ks * 8 + tig];
            af[1] = pw[(g + 8) * 68 + ks * 8 + tig];
            af[2] = pw[g * 68 + ks * 8 + tig + 4];
            af[3] = pw[(g + 8) * 68 + ks * 8 + tig + 4];
            #pragma unroll
            for (int nt = 0; nt < 8; nt++) {
                unsigned bf2[2];
                bf2[0] = KV[(64 + ks * 8 + tig) * 68 + nt * 8 + g];
                bf2[1] = KV[(64 + ks * 8 + tig + 4) * 68 + nt * 8 + g];
                mma8(o[nt], af, bf2);
            }
        }
        __syncthreads();

        // ---- store prefetched next tile ----
        if (nx) {
            #pragma unroll
            for (int i = 0; i < 4; i++) {
                int r = lr + i * 16;
                unsigned* dk = &KV[r * 68 + lc];
                dk[0] = f2tf(kpre[i].x); dk[1] = f2tf(kpre[i].y);
                dk[2] = f2tf(kpre[i].z); dk[3] = f2tf(kpre[i].w);
                unsigned* dv = &KV[(64 + r) * 68 + lc];
                dv[0] = f2tf(vpre[i].x); dv[1] = f2tf(vpre[i].y);
                dv[2] = f2tf(vpre[i].z); dv[3] = f2tf(vpre[i].w);
            }
            if (tid < 64) bsL[tid] = bpre * LOG2E;
            __syncthreads();
        }
    }

    // ---- normalize + write ----
    float inv0 = 1.f / l0, inv1 = 1.f / l1;
    int row0 = b * S + q0 + warp * 16 + g;
    float* ob0 = Op + o_off + h * 64 + (size_t)row0 * o_ld;
    float* ob1 = Op + o_off + h * 64 + (size_t)(row0 + 8) * o_ld;
    #pragma unroll
    for (int nt = 0; nt < 8; nt++) {
        int col = nt * 8 + 2 * tig;
        *(float2*)(ob0 + col) = make_float2(o[nt][0] * inv0, o[nt][1] * inv0);
        *(float2*)(ob1 + col) = make_float2(o[nt][2] * inv1, o[nt][3] * inv1);
    }
}

// ---------------------------------------------------------------------------
// Fused survival MLPs, 8 tokens per block (weight traffic / 8)
// ---------------------------------------------------------------------------
__global__ __launch_bounds__(128) void mlp_surv2(
    const float* __restrict__ H, const int* __restrict__ mask,
    const float* __restrict__ nw1, const float* __restrict__ nb1,
    const float* __restrict__ nw2, const float* __restrict__ nb2,
    const float* __restrict__ mw1, const float* __restrict__ mb1,
    const float* __restrict__ mw2, const float* __restrict__ mb2,
    const float* __restrict__ dw1, const float* __restrict__ db1,
    const float* __restrict__ dw2, const float* __restrict__ db2,
    float* __restrict__ biasM)
{
    __shared__ float hs[8][256];
    __shared__ float red[24][128];   // [head*8 + tok][thread]

    int t = threadIdx.x;
    int tok0 = blockIdx.x * 8;

    #pragma unroll
    for (int i = 0; i < 16; i++) {
        int idx = t + i * 128; int tk = idx >> 8, c = idx & 255;
        hs[tk][c] = H[(size_t)(tok0 + tk) * 256 + c];
    }
    __syncthreads();

    const float* wn = nw1 + (size_t)t * 256;
    const float* wm = mw1 + (size_t)t * 256;
    const float* wd = dw1 + (size_t)t * 256;
    float sn[8], smu[8], sd[8];
    #pragma unroll
    for (int k = 0; k < 8; k++) { sn[k] = 0.f; smu[k] = 0.f; sd[k] = 0.f; }
    for (int i = 0; i < 256; i++) {
        float a = wn[i], bb = wm[i], c = wd[i];
        #pragma unroll
        for (int k = 0; k < 8; k++) {
            float hv = hs[k][i];
            sn[k] += a * hv; smu[k] += bb * hv; sd[k] += c * hv;
        }
    }
    float a1 = nb1[t], a2 = nw2[t], b1 = mb1[t], b2 = mw2[t], c1 = db1[t], c2 = dw2[t];
    #pragma unroll
    for (int k = 0; k < 8; k++) {
        red[k][t]      = fmaxf(sn[k]  + a1, 0.f) * a2;
        red[8 + k][t]  = fmaxf(smu[k] + b1, 0.f) * b2;
        red[16 + k][t] = fmaxf(sd[k]  + c1, 0.f) * c2;
    }
    __syncthreads();

    for (int s2 = 64; s2 > 0; s2 >>= 1) {
        for (int j = t; j < 24 * s2; j += 128) {
            int row = j / s2, c = j % s2;
            red[row][c] += red[row][c + s2];
        }
        __syncthreads();
    }

    if (t < 8) {
        float zn = red[t][0] + nb2[0];
        float zm = red[8 + t][0] + mb2[0];
        float zd = red[16 + t][0] + db2[0];
        float n     = (zn > 20.f) ? zn : log1pf(__expf(zn));
        float mu    = 1.f / (1.f + __expf(-zm));
        float delta = fmaxf(zd, 0.f);
        float surv  = logf(n + 1e-8f) + logf(mu + 1e-8f) - delta;
        biasM[tok0 + t] = 0.1f * surv + ((mask[tok0 + t] > 0) ? 0.f : -1e9f);
    }
}

// ---------------------------------------------------------------------------
// Launch
// ---------------------------------------------------------------------------
extern "C" void kernel_launch(void* const* d_in, const int* in_sizes, int n_in,
                              void* d_out, int out_size)
{
    const float* x        = (const float*)d_in[0];
    const int*   mask     = (const int*)  d_in[1];
    const float* qw = (const float*)d_in[2],  *qb = (const float*)d_in[3];
    const float* kw = (const float*)d_in[4],  *kb = (const float*)d_in[5];
    const float* vw = (const float*)d_in[6],  *vb = (const float*)d_in[7];
    const float* ow = (const float*)d_in[8],  *ob = (const float*)d_in[9];
    const float* sp_w = (const float*)d_in[10], *sp_b = (const float*)d_in[11];
    const float* sa_in_w  = (const float*)d_in[12], *sa_in_b  = (const float*)d_in[13];
    const float* sa_out_w = (const float*)d_in[14], *sa_out_b = (const float*)d_in[15];
    const float* nw1 = (const float*)d_in[16], *nb1 = (const float*)d_in[17];
    const float* nw2 = (const float*)d_in[18], *nb2 = (const float*)d_in[19];
    const float* mw1 = (const float*)d_in[20], *mb1 = (const float*)d_in[21];
    const float* mw2 = (const float*)d_in[22], *mb2 = (const float*)d_in[23];
    const float* dw1 = (const float*)d_in[24], *db1 = (const float*)d_in[25];
    const float* dw2 = (const float*)d_in[26], *db2 = (const float*)d_in[27];
    float* out = (float*)d_out;

    float *Q, *K, *V, *attn, *h0, *qkvs, *sattn, *h1, *biasS, *biasM;
    cudaGetSymbolAddress((void**)&Q,     g_Q);
    cudaGetSymbolAddress((void**)&K,     g_K);
    cudaGetSymbolAddress((void**)&V,     g_V);
    cudaGetSymbolAddress((void**)&attn,  g_attn);
    cudaGetSymbolAddress((void**)&h0,    g_h0);
    cudaGetSymbolAddress((void**)&qkvs,  g_qkvs);
    cudaGetSymbolAddress((void**)&sattn, g_sattn);
    cudaGetSymbolAddress((void**)&h1,    g_h1);
    cudaGetSymbolAddress((void**)&biasS, g_biasS);
    cudaGetSymbolAddress((void**)&biasM, g_biasM);

    const int M = MTOK, S = SEQ, B = BATCH, H = HDIM, I = IDIM;

    const int SM128 = (2 * 128 * 36 + 2 * 128 * 36) * 4;   // 73728
    const int SM64  = (2 * 64 * 36 + 2 * 128 * 36) * 4;    // 55296
    const int SMATT = (2 * 128 * 68 + 64) * 4;             // 69888

    cudaFuncSetAttribute(gemm2<128>, cudaFuncAttributeMaxDynamicSharedMemorySize, SM128);
    cudaFuncSetAttribute(gemm2<64>,  cudaFuncAttributeMaxDynamicSharedMemorySize, SM64);
    cudaFuncSetAttribute(attn2,      cudaFuncAttributeMaxDynamicSharedMemorySize, SMATT);

    // scorer path
    mask_bias_kernel<<<(M + 255) / 256, 256>>>(mask, biasS, M);
    gemm2<64><<<dim3(I / 128, M / 64), 256, SM64>>>(x, sp_w, sp_b, h0, M, I, H);
    gemm2<128><<<dim3(3 * I / 128, M / 128), 256, SM128>>>(h0, sa_in_w, sa_in_b, qkvs, M, 3 * I, I);
    attn2<<<dim3(S / 128, 4, B), 256, SMATT>>>(qkvs, qkvs, qkvs, biasS, sattn,
                                               S, 3 * I, 0, I, 2 * I, I, 0);
    gemm2<64><<<dim3(I / 128, M / 64), 256, SM64>>>(sattn, sa_out_w, sa_out_b, h1, M, I, I);
    mlp_surv2<<<M / 8, 128>>>(h1, mask, nw1, nb1, nw2, nb2,
                              mw1, mb1, mw2, mb2, dw1, db1, dw2, db2, biasM);

    // main path
    gemm2<128><<<dim3(H / 128, M / 128), 256, SM128>>>(x, qw, qb, Q, M, H, H);
    gemm2<128><<<dim3(H / 128, M / 128), 256, SM128>>>(x, kw, kb, K, M, H, H);
    gemm2<128><<<dim3(H / 128, M / 128), 256, SM128>>>(x, vw, vb, V, M, H, H);
    attn2<<<dim3(S / 128, 12, B), 256, SMATT>>>(Q, K, V, biasM, attn,
                                                S, H, 0, 0, 0, H, 0);
    gemm2<128><<<dim3(H / 128, M / 128), 256, SM128>>>(attn, ow, ob, out, M, H, H);
}